// round 4
// baseline (speedup 1.0000x reference)
#include <cuda_runtime.h>
#include <cstdint>
#include <math.h>

#define Nn 80000
#define Uu 40000
#define Dd 128
#define Ee 1600000
#define Lh 17   // K+1 keys

// ---------------- scratch (static device globals: no allocation) ----------------
__device__ float g_tmp[Nn * Dd];
__device__ float g_QT[2 * Nn * Dd];
__device__ float g_KT[2 * Nn * Dd];
__device__ float g_VT[2 * Nn * Dd];
__device__ float g_O[Nn * Dd];
__device__ float g_e[Nn * Dd];
__device__ float g_total[Nn * Dd];
__device__ float g_posK[2 * Lh * Dd];
__device__ float g_posV[2 * Lh * Dd];
__device__ float g_posQ0[2 * Dd];
__device__ int   g_cnt[Nn];
__device__ int   g_rowptr[Nn + 1];
__device__ int   g_scol[Ee];
__device__ float g_sval[Ee];

// ---------------- f32x2 packed-FMA helpers (PTX ISA 8.6, base sm_100 family) ----
__device__ __forceinline__ void fma2(unsigned long long& c, unsigned long long a,
                                     unsigned long long b) {
    asm("fma.rn.f32x2 %0, %1, %2, %0;" : "+l"(c) : "l"(a), "l"(b));
}
__device__ __forceinline__ unsigned long long dup2(float x) {
    unsigned long long r;
    asm("mov.b64 %0, {%1, %1};" : "=l"(r) : "f"(x));
    return r;
}
__device__ __forceinline__ float lo32(unsigned long long v) {
    return __uint_as_float((unsigned)(v & 0xffffffffull));
}
__device__ __forceinline__ float hi32(unsigned long long v) {
    return __uint_as_float((unsigned)(v >> 32));
}

// ---------------- init: e = concat(user,item); total = e ----------------
__global__ void k_init(const float* __restrict__ ue, const float* __restrict__ ie) {
    int i = blockIdx.x * blockDim.x + threadIdx.x;
    if (i >= Nn * Dd) return;
    float v = (i < Uu * Dd) ? ue[i] : ie[i - Uu * Dd];
    g_e[i] = v;
    g_total[i] = v;
}

// ---------------- CSR build ----------------
__global__ void k_hist(const int* __restrict__ rows) {
    int i = blockIdx.x * blockDim.x + threadIdx.x;
    if (i < Ee) atomicAdd(&g_cnt[rows[i]], 1);
}
__global__ void k_scan() {
    __shared__ int ssum[1024];
    const int t = threadIdx.x;
    const int CH = (Nn + 1023) / 1024;
    int lo = t * CH;
    int hi = lo + CH; if (hi > Nn) hi = Nn;
    if (lo > Nn) lo = Nn;
    int s = 0;
    for (int r = lo; r < hi; r++) s += g_cnt[r];
    ssum[t] = s;
    __syncthreads();
    for (int off = 1; off < 1024; off <<= 1) {
        int v = (t >= off) ? ssum[t - off] : 0;
        __syncthreads();
        ssum[t] += v;
        __syncthreads();
    }
    int base = (t == 0) ? 0 : ssum[t - 1];
    for (int r = lo; r < hi; r++) { g_rowptr[r] = base; base += g_cnt[r]; }
    if (t == 1023) g_rowptr[Nn] = ssum[1023];
}
__global__ void k_scatter(const int* __restrict__ rows, const int* __restrict__ cols,
                          const float* __restrict__ vals) {
    int i = blockIdx.x * blockDim.x + threadIdx.x;
    if (i >= Ee) return;
    int r = rows[i];
    int p = g_rowptr[r] + atomicAdd(&g_cnt[r], 1);
    g_scol[p] = cols[i];
    g_sval[p] = vals[i];
}

// ---------------- SpMM (CSR, one warp per row) ----------------
__global__ void __launch_bounds__(256) k_spmm() {
    int w = (blockIdx.x * 256 + threadIdx.x) >> 5;
    if (w >= Nn) return;
    int lane = threadIdx.x & 31;
    int j0 = g_rowptr[w], j1 = g_rowptr[w + 1];
    float4 acc = make_float4(0.f, 0.f, 0.f, 0.f);
    for (int j = j0; j < j1; j++) {
        int   c = g_scol[j];
        float v = g_sval[j];
        float4 ev = *(const float4*)&g_e[c * Dd + lane * 4];
        acc.x += v * ev.x; acc.y += v * ev.y; acc.z += v * ev.z; acc.w += v * ev.w;
    }
    *(float4*)&g_tmp[w * Dd + lane * 4] = acc;
}

// ---------------- projected positional embeddings ----------------
__global__ void k_pos(const float* __restrict__ pos, const float* __restrict__ u_in_w,
                      const float* __restrict__ i_in_w) {
    int bid = blockIdx.x;
    int set = bid / 35;
    int r = bid % 35;
    const float* w = set ? i_in_w : u_in_w;
    const float* prow;
    float* out;
    if (r == 0)      { prow = pos;                 w += 0;           out = &g_posQ0[set * Dd]; }
    else if (r < 18) { int l = r - 1;  prow = pos + l * Dd; w += Dd * Dd;     out = &g_posK[(set * Lh + l) * Dd]; }
    else             { int l = r - 18; prow = pos + l * Dd; w += 2 * Dd * Dd; out = &g_posV[(set * Lh + l) * Dd]; }
    __shared__ float p[Dd];
    p[threadIdx.x] = prow[threadIdx.x];
    __syncthreads();
    int j = threadIdx.x;
    float acc = 0.f;
    #pragma unroll 4
    for (int k = 0; k < Dd; k++) acc += p[k] * w[j * 128 + k];
    out[j] = acc;
}

// ---------------- GEMM (f32x2 packed FMA): out[r,:] = in[r,:] @ w^T + bias ------
// CTA: 128 rows x 128 cols, 256 threads, thread tile 8x8 (4 row-pairs x 8 cols).
// K chunked at 64: smem = A-chunk transposed (xs[k][r]) + W-chunk transposed (ws[k][c]).
__global__ void __launch_bounds__(256, 2) k_gemm2(const float* __restrict__ in,
                                                  const float* __restrict__ w,
                                                  const float* __restrict__ bias,
                                                  float* __restrict__ out,
                                                  int rowStart, int rowLimit,
                                                  const float* __restrict__ resid,
                                                  float* __restrict__ total) {
    extern __shared__ float sm[];
    float* xs = sm;            // [64][128]
    float* ws = sm + 64 * 128; // [64][128]
    const int t = threadIdx.x;
    const int row0 = rowStart + blockIdx.x * 128;
    const int r0 = (t >> 4) * 8;      // 16 row-groups
    const int c0 = (t & 15) * 8;      // 16 col-groups

    unsigned long long acc[4][8];
    #pragma unroll
    for (int i = 0; i < 4; i++)
        #pragma unroll
        for (int j = 0; j < 8; j++) acc[i][j] = 0ull;

    const int rL = t & 127;           // staged row / weight col
    const int kh = (t >> 7) * 32;     // k half within 64-chunk
    const bool vload = (row0 + rL) < rowLimit;

    for (int kc = 0; kc < 128; kc += 64) {
        // stage A chunk (transposed)
        const float* asrc = &in[(size_t)(row0 + rL) * 128 + kc + kh];
        #pragma unroll
        for (int i = 0; i < 8; i++) {
            float4 v = vload ? *(const float4*)&asrc[i * 4] : make_float4(0.f, 0.f, 0.f, 0.f);
            xs[(kh + i * 4 + 0) * 128 + rL] = v.x;
            xs[(kh + i * 4 + 1) * 128 + rL] = v.y;
            xs[(kh + i * 4 + 2) * 128 + rL] = v.z;
            xs[(kh + i * 4 + 3) * 128 + rL] = v.w;
        }
        // stage W chunk (transposed): ws[k][c] = w[c*128 + kc + k]
        const float* wsrc = &w[(size_t)rL * 128 + kc + kh];
        #pragma unroll
        for (int i = 0; i < 8; i++) {
            float4 v = *(const float4*)&wsrc[i * 4];
            ws[(kh + i * 4 + 0) * 128 + rL] = v.x;
            ws[(kh + i * 4 + 1) * 128 + rL] = v.y;
            ws[(kh + i * 4 + 2) * 128 + rL] = v.z;
            ws[(kh + i * 4 + 3) * 128 + rL] = v.w;
        }
        __syncthreads();

        #pragma unroll 4
        for (int k = 0; k < 64; k++) {
            const ulonglong2 A0 = *(const ulonglong2*)&xs[k * 128 + r0];
            const ulonglong2 A1 = *(const ulonglong2*)&xs[k * 128 + r0 + 4];
            const float4 w0 = *(const float4*)&ws[k * 128 + c0];
            const float4 w1 = *(const float4*)&ws[k * 128 + c0 + 4];
            unsigned long long b[8];
            b[0] = dup2(w0.x); b[1] = dup2(w0.y); b[2] = dup2(w0.z); b[3] = dup2(w0.w);
            b[4] = dup2(w1.x); b[5] = dup2(w1.y); b[6] = dup2(w1.z); b[7] = dup2(w1.w);
            #pragma unroll
            for (int j = 0; j < 8; j++) {
                fma2(acc[0][j], A0.x, b[j]);
                fma2(acc[1][j], A0.y, b[j]);
                fma2(acc[2][j], A1.x, b[j]);
                fma2(acc[3][j], A1.y, b[j]);
            }
        }
        __syncthreads();
    }

    // epilogue
    float4 bv0 = *(const float4*)&bias[c0];
    float4 bv1 = *(const float4*)&bias[c0 + 4];
    #pragma unroll
    for (int rp = 0; rp < 4; rp++) {
        #pragma unroll
        for (int h2 = 0; h2 < 2; h2++) {
            int r = row0 + r0 + rp * 2 + h2;
            if (r >= rowLimit) continue;
            float v[8];
            #pragma unroll
            for (int j = 0; j < 8; j++) v[j] = h2 ? hi32(acc[rp][j]) : lo32(acc[rp][j]);
            size_t ofs = (size_t)r * 128 + c0;
            float4 o0 = make_float4(v[0] + bv0.x, v[1] + bv0.y, v[2] + bv0.z, v[3] + bv0.w);
            float4 o1 = make_float4(v[4] + bv1.x, v[5] + bv1.y, v[6] + bv1.z, v[7] + bv1.w);
            if (resid) {
                float4 ra = *(const float4*)&resid[ofs];
                float4 rb = *(const float4*)&resid[ofs + 4];
                o0.x += ra.x; o0.y += ra.y; o0.z += ra.z; o0.w += ra.w;
                o1.x += rb.x; o1.y += rb.y; o1.z += rb.z; o1.w += rb.w;
            }
            *(float4*)&out[ofs] = o0;
            *(float4*)&out[ofs + 4] = o1;
            if (total) {
                float4 ta = *(const float4*)&total[ofs];
                float4 tb = *(const float4*)&total[ofs + 4];
                ta.x += o0.x; ta.y += o0.y; ta.z += o0.z; ta.w += o0.w;
                tb.x += o1.x; tb.y += o1.y; tb.z += o1.z; tb.w += o1.w;
                *(float4*)&total[ofs] = ta;
                *(float4*)&total[ofs + 4] = tb;
            }
        }
    }
}

// ---------------- attention: one warp per node ----------------
__global__ void __launch_bounds__(256) k_attn(const int* __restrict__ samples) {
    int w = (blockIdx.x * 256 + threadIdx.x) >> 5;
    if (w >= Nn) return;
    int lane = threadIdx.x & 31;
    int set = (w < Uu) ? 0 : 1;
    const float* Qt = &g_QT[set * (Nn * Dd)];
    const float* Kt = &g_KT[set * (Nn * Dd)];
    const float* Vt = &g_VT[set * (Nn * Dd)];
    const float* pk = &g_posK[set * Lh * Dd];
    const float* pv = &g_posV[set * Lh * Dd];
    const float* pq = &g_posQ0[set * Dd];
    int c4 = lane * 4;

    float4 qv = *(const float4*)&Qt[w * Dd + c4];
    float4 pqv = *(const float4*)&pq[c4];
    float qx = qv.x + pqv.x, qy = qv.y + pqv.y, qz = qv.z + pqv.z, qw = qv.w + pqv.w;

    int sidx[Lh];
    sidx[0] = w;
    #pragma unroll
    for (int l = 1; l < Lh; l++) sidx[l] = samples[w * 16 + (l - 1)];

    const float scale = 0.17677669529663687f;
    float sc[Lh];
    #pragma unroll
    for (int l = 0; l < Lh; l++) {
        float4 kv = *(const float4*)&Kt[sidx[l] * Dd + c4];
        float4 pkv = *(const float4*)&pk[l * Dd + c4];
        float d = qx * (kv.x + pkv.x) + qy * (kv.y + pkv.y) + qz * (kv.z + pkv.z) + qw * (kv.w + pkv.w);
        d += __shfl_xor_sync(0xffffffffu, d, 1);
        d += __shfl_xor_sync(0xffffffffu, d, 2);
        d += __shfl_xor_sync(0xffffffffu, d, 4);
        sc[l] = d * scale;
    }
    float m = sc[0];
    #pragma unroll
    for (int l = 1; l < Lh; l++) m = fmaxf(m, sc[l]);
    float s = 0.f;
    #pragma unroll
    for (int l = 0; l < Lh; l++) { sc[l] = __expf(sc[l] - m); s += sc[l]; }
    float inv = 1.f / s;

    float ox = 0.f, oy = 0.f, oz = 0.f, ow = 0.f;
    #pragma unroll
    for (int l = 0; l < Lh; l++) {
        float wgt = sc[l] * inv;
        float4 vv = *(const float4*)&Vt[sidx[l] * Dd + c4];
        float4 pvv = *(const float4*)&pv[l * Dd + c4];
        ox += wgt * (vv.x + pvv.x); oy += wgt * (vv.y + pvv.y);
        oz += wgt * (vv.z + pvv.z); ow += wgt * (vv.w + pvv.w);
    }
    *(float4*)&g_O[w * Dd + c4] = make_float4(ox, oy, oz, ow);
}

// ---------------- output ----------------
__global__ void k_out(float* __restrict__ out) {
    int i = blockIdx.x * blockDim.x + threadIdx.x;
    if (i >= Nn * Dd) return;
    float v = g_total[i];
    out[i] = v;
    out[Nn * Dd + i] = v;
}

extern "C" void kernel_launch(void* const* d_in, const int* in_sizes, int n_in,
                              void* d_out, int out_size) {
    (void)in_sizes; (void)n_in; (void)out_size;
    const int*   adj_rows = (const int*)d_in[0];
    const int*   adj_cols = (const int*)d_in[1];
    const float* adj_vals = (const float*)d_in[2];
    const int*   samples  = (const int*)d_in[3];
    const float* user_emb = (const float*)d_in[4];
    const float* item_emb = (const float*)d_in[5];
    const float* pos_emb  = (const float*)d_in[6];
    const float* u_in_w   = (const float*)d_in[7];
    const float* u_in_b   = (const float*)d_in[8];
    const float* u_out_w  = (const float*)d_in[9];
    const float* u_out_b  = (const float*)d_in[10];
    const float* i_in_w   = (const float*)d_in[11];
    const float* i_in_b   = (const float*)d_in[12];
    const float* i_out_w  = (const float*)d_in[13];
    const float* i_out_b  = (const float*)d_in[14];
    float* out = (float*)d_out;

    const int SMB = 64 * 128 * 2 * sizeof(float);  // 64KB
    cudaFuncSetAttribute(k_gemm2, cudaFuncAttributeMaxDynamicSharedMemorySize, SMB);

    void *cntP, *tmpP, *qP, *ktP, *vtP, *oP, *eP, *totP;
    cudaGetSymbolAddress(&cntP, g_cnt);
    cudaGetSymbolAddress(&tmpP, g_tmp);
    cudaGetSymbolAddress(&qP, g_QT);
    cudaGetSymbolAddress(&ktP, g_KT);
    cudaGetSymbolAddress(&vtP, g_VT);
    cudaGetSymbolAddress(&oP, g_O);
    cudaGetSymbolAddress(&eP, g_e);
    cudaGetSymbolAddress(&totP, g_total);
    float* gTmp = (float*)tmpP;
    float* gQ  = (float*)qP;
    float* gKT = (float*)ktP;
    float* gVT = (float*)vtP;
    float* gO  = (float*)oP;
    float* gE  = (float*)eP;
    float* gTot = (float*)totP;

    // CSR build (constant per call; rebuilt for determinism)
    cudaMemsetAsync(cntP, 0, Nn * sizeof(int));
    k_hist<<<(Ee + 255) / 256, 256>>>(adj_rows);
    k_scan<<<1, 1024>>>();
    cudaMemsetAsync(cntP, 0, Nn * sizeof(int));
    k_scatter<<<(Ee + 255) / 256, 256>>>(adj_rows, adj_cols, adj_vals);

    k_init<<<(Nn * Dd) / 256, 256>>>(user_emb, item_emb);
    k_pos<<<70, 128>>>(pos_emb, u_in_w, i_in_w);

    const int HB = 313;  // ceil(40000/128)
    const int FB = 625;  // 80000/128
    for (int blk = 0; blk < 2; blk++) {
        k_spmm<<<(Nn * 32) / 256, 256>>>();
        // Q: per-set over own rows only
        k_gemm2<<<HB, 256, SMB>>>(gTmp, u_in_w, u_in_b, gQ, 0,  Uu, nullptr, nullptr);
        k_gemm2<<<HB, 256, SMB>>>(gTmp, i_in_w, i_in_b, gQ, Uu, Nn, nullptr, nullptr);
        // K,V: both weight sets over ALL N rows
        k_gemm2<<<FB, 256, SMB>>>(gTmp, u_in_w + Dd * Dd,     u_in_b + Dd,     gKT,           0, Nn, nullptr, nullptr);
        k_gemm2<<<FB, 256, SMB>>>(gTmp, i_in_w + Dd * Dd,     i_in_b + Dd,     gKT + Nn * Dd, 0, Nn, nullptr, nullptr);
        k_gemm2<<<FB, 256, SMB>>>(gTmp, u_in_w + 2 * Dd * Dd, u_in_b + 2 * Dd, gVT,           0, Nn, nullptr, nullptr);
        k_gemm2<<<FB, 256, SMB>>>(gTmp, i_in_w + 2 * Dd * Dd, i_in_b + 2 * Dd, gVT + Nn * Dd, 0, Nn, nullptr, nullptr);
        k_attn<<<(Nn * 32) / 256, 256>>>(samples);
        // out-projection + residual(tmp) -> new e; total += e
        k_gemm2<<<HB, 256, SMB>>>(gO, u_out_w, u_out_b, gE, 0,  Uu, gTmp, gTot);
        k_gemm2<<<HB, 256, SMB>>>(gO, i_out_w, i_out_b, gE, Uu, Nn, gTmp, gTot);
    }
    k_out<<<(Nn * Dd) / 256, 256>>>(out);
}

// round 5
// speedup vs baseline: 1.2619x; 1.2619x over previous
#include <cuda_runtime.h>
#include <cuda_bf16.h>
#include <cstdint>
#include <math.h>

#define Nn 80000
#define Uu 40000
#define Dd 128
#define Ee 1600000
#define Lh 17   // K+1 keys

// ---------------- scratch (static device globals: no allocation) ----------------
__device__ float g_tmp[Nn * Dd];
__device__ float g_QT[2 * Nn * Dd];
__device__ float g_KT[2 * Nn * Dd];
__device__ float g_VT[2 * Nn * Dd];
__device__ float g_O[Nn * Dd];
__device__ float g_e[Nn * Dd];
__device__ float g_total[Nn * Dd];
__device__ float g_posK[2 * Lh * Dd];
__device__ float g_posV[2 * Lh * Dd];
__device__ float g_posQ0[2 * Dd];
__device__ int   g_cnt[Nn];
__device__ int   g_rowptr[Nn + 1];
__device__ int   g_scol[Ee];
__device__ float g_sval[Ee];
// 8 weight matrices split to bf16 {hi,lo}, plain row-major [128][128]
__device__ __nv_bfloat16 g_Bh[8 * 16384];
__device__ __nv_bfloat16 g_Bl[8 * 16384];

// ---------------- PTX helpers (all baseline PTX, no sm_103a-gated features) -----
__device__ __forceinline__ uint32_t smem_to_u32(const void* p) {
    uint32_t a;
    asm("{ .reg .u64 tmp; cvta.to.shared.u64 tmp, %1; cvt.u32.u64 %0, tmp; }" : "=r"(a) : "l"(p));
    return a;
}
__device__ __forceinline__ void ldm4(uint32_t* r, uint32_t addr) {
    asm volatile("ldmatrix.sync.aligned.m8n8.x4.shared.b16 {%0,%1,%2,%3}, [%4];"
                 : "=r"(r[0]), "=r"(r[1]), "=r"(r[2]), "=r"(r[3]) : "r"(addr));
}
__device__ __forceinline__ void mma_bf16(float* c, const uint32_t* a, uint32_t b0, uint32_t b1) {
    asm volatile("mma.sync.aligned.m16n8k16.row.col.f32.bf16.bf16.f32 "
                 "{%0,%1,%2,%3}, {%4,%5,%6,%7}, {%8,%9}, {%0,%1,%2,%3};"
                 : "+f"(c[0]), "+f"(c[1]), "+f"(c[2]), "+f"(c[3])
                 : "r"(a[0]), "r"(a[1]), "r"(a[2]), "r"(a[3]), "r"(b0), "r"(b1));
}
__device__ __forceinline__ uint32_t lds32(uint32_t addr) {
    uint32_t v;
    asm volatile("ld.shared.b32 %0, [%1];" : "=r"(v) : "r"(addr));
    return v;
}

#define ASTRIDE 136   // bf16 elems per smem row (128 + 8 pad -> conflict-free ldmatrix)

// One pass over all 8 k-steps for one B flavor.  If alAddr != 0, also accumulates Al*B.
__device__ __forceinline__ void mma_phase(uint32_t ahAddr, uint32_t alAddr, uint32_t bAddr,
                                          int warp_m, int warp_n, int lane,
                                          float (*acc)[4]) {
    const int g = lane >> 2, q = lane & 3;
    const int arow = lane & 15, ahalf = (lane >> 4) << 3;
    #pragma unroll
    for (int ks = 0; ks < 8; ks++) {
        uint32_t b0[4], b1[4];
        #pragma unroll
        for (int tn = 0; tn < 4; tn++) {
            uint32_t baddr = bAddr + (uint32_t)(((warp_n * 32 + tn * 8 + g) * ASTRIDE + ks * 16 + 2 * q) << 1);
            b0[tn] = lds32(baddr);
            b1[tn] = lds32(baddr + 16);
        }
        #pragma unroll
        for (int tm = 0; tm < 4; tm++) {
            uint32_t a[4];
            uint32_t aaddr = ahAddr + (uint32_t)(((warp_m * 64 + tm * 16 + arow) * ASTRIDE + ks * 16 + ahalf) << 1);
            ldm4(a, aaddr);
            #pragma unroll
            for (int tn = 0; tn < 4; tn++) mma_bf16(acc[tm * 4 + tn], a, b0[tn], b1[tn]);
        }
        if (alAddr) {
            #pragma unroll
            for (int tm = 0; tm < 4; tm++) {
                uint32_t a[4];
                uint32_t aaddr = alAddr + (uint32_t)(((warp_m * 64 + tm * 16 + arow) * ASTRIDE + ks * 16 + ahalf) << 1);
                ldm4(a, aaddr);
                #pragma unroll
                for (int tn = 0; tn < 4; tn++) mma_bf16(acc[tm * 4 + tn], a, b0[tn], b1[tn]);
            }
        }
    }
}

// stage 128-row fp32 tile -> smem bf16 hi/lo (2 threads per row)
__device__ __forceinline__ void stage_A(__nv_bfloat16* AhS, __nv_bfloat16* AlS,
                                        const float* __restrict__ src128, int row0,
                                        int rowLimit, int t) {
    const int r = t >> 1, h = (t & 1) * 64;
    const bool valid = (row0 + r) < rowLimit;
    const float* src = &src128[(size_t)(row0 + r) * 128 + h];
    #pragma unroll
    for (int i = 0; i < 16; i++) {
        float4 v = valid ? *(const float4*)&src[i * 4] : make_float4(0.f, 0.f, 0.f, 0.f);
        __nv_bfloat16 h0 = __float2bfloat16(v.x), h1 = __float2bfloat16(v.y);
        __nv_bfloat16 h2 = __float2bfloat16(v.z), h3 = __float2bfloat16(v.w);
        __nv_bfloat16 l0 = __float2bfloat16(v.x - __bfloat162float(h0));
        __nv_bfloat16 l1 = __float2bfloat16(v.y - __bfloat162float(h1));
        __nv_bfloat16 l2 = __float2bfloat16(v.z - __bfloat162float(h2));
        __nv_bfloat16 l3 = __float2bfloat16(v.w - __bfloat162float(h3));
        int idx = r * ASTRIDE + h + i * 4;
        *(__nv_bfloat162*)&AhS[idx]     = __halves2bfloat162(h0, h1);
        *(__nv_bfloat162*)&AhS[idx + 2] = __halves2bfloat162(h2, h3);
        *(__nv_bfloat162*)&AlS[idx]     = __halves2bfloat162(l0, l1);
        *(__nv_bfloat162*)&AlS[idx + 2] = __halves2bfloat162(l2, l3);
    }
}

// stage 128x128 bf16 weight (plain row-major) -> padded smem
__device__ __forceinline__ void stage_B(__nv_bfloat16* BsS, const __nv_bfloat16* __restrict__ src, int t) {
    const int r = t >> 1, h = (t & 1) * 64;
    const uint4* s = (const uint4*)&src[r * 128 + h];
    #pragma unroll
    for (int i = 0; i < 8; i++)
        *(uint4*)&BsS[r * ASTRIDE + h + i * 8] = s[i];
}

// ---------------- init: e = concat(user,item); total = e ----------------
__global__ void k_init(const float* __restrict__ ue, const float* __restrict__ ie) {
    int i = blockIdx.x * blockDim.x + threadIdx.x;
    if (i >= Nn * Dd) return;
    float v = (i < Uu * Dd) ? ue[i] : ie[i - Uu * Dd];
    g_e[i] = v;
    g_total[i] = v;
}

// ---------------- CSR build ----------------
__global__ void k_hist(const int* __restrict__ rows) {
    int i = blockIdx.x * blockDim.x + threadIdx.x;
    if (i < Ee) atomicAdd(&g_cnt[rows[i]], 1);
}
__global__ void k_scan() {
    __shared__ int ssum[1024];
    const int t = threadIdx.x;
    const int CH = (Nn + 1023) / 1024;
    int lo = t * CH;
    int hi = lo + CH; if (hi > Nn) hi = Nn;
    if (lo > Nn) lo = Nn;
    int s = 0;
    for (int r = lo; r < hi; r++) s += g_cnt[r];
    ssum[t] = s;
    __syncthreads();
    for (int off = 1; off < 1024; off <<= 1) {
        int v = (t >= off) ? ssum[t - off] : 0;
        __syncthreads();
        ssum[t] += v;
        __syncthreads();
    }
    int base = (t == 0) ? 0 : ssum[t - 1];
    for (int r = lo; r < hi; r++) { g_rowptr[r] = base; base += g_cnt[r]; }
    if (t == 1023) g_rowptr[Nn] = ssum[1023];
}
__global__ void k_scatter(const int* __restrict__ rows, const int* __restrict__ cols,
                          const float* __restrict__ vals) {
    int i = blockIdx.x * blockDim.x + threadIdx.x;
    if (i >= Ee) return;
    int r = rows[i];
    int p = g_rowptr[r] + atomicAdd(&g_cnt[r], 1);
    g_scol[p] = cols[i];
    g_sval[p] = vals[i];
}

// ---------------- SpMM (CSR, one warp per row) ----------------
__global__ void __launch_bounds__(256) k_spmm() {
    int w = (blockIdx.x * 256 + threadIdx.x) >> 5;
    if (w >= Nn) return;
    int lane = threadIdx.x & 31;
    int j0 = g_rowptr[w], j1 = g_rowptr[w + 1];
    float4 acc = make_float4(0.f, 0.f, 0.f, 0.f);
    for (int j = j0; j < j1; j++) {
        int   c = g_scol[j];
        float v = g_sval[j];
        float4 ev = *(const float4*)&g_e[c * Dd + lane * 4];
        acc.x += v * ev.x; acc.y += v * ev.y; acc.z += v * ev.z; acc.w += v * ev.w;
    }
    *(float4*)&g_tmp[w * Dd + lane * 4] = acc;
}

// ---------------- projected positional embeddings (fp32) ----------------
__global__ void k_pos(const float* __restrict__ pos, const float* __restrict__ u_in_w,
                      const float* __restrict__ i_in_w) {
    int bid = blockIdx.x;
    int set = bid / 35;
    int r = bid % 35;
    const float* w = set ? i_in_w : u_in_w;
    const float* prow;
    float* out;
    if (r == 0)      { prow = pos;                 w += 0;           out = &g_posQ0[set * Dd]; }
    else if (r < 18) { int l = r - 1;  prow = pos + l * Dd; w += Dd * Dd;     out = &g_posK[(set * Lh + l) * Dd]; }
    else             { int l = r - 18; prow = pos + l * Dd; w += 2 * Dd * Dd; out = &g_posV[(set * Lh + l) * Dd]; }
    __shared__ float p[Dd];
    p[threadIdx.x] = prow[threadIdx.x];
    __syncthreads();
    int j = threadIdx.x;
    float acc = 0.f;
    #pragma unroll 4
    for (int k = 0; k < Dd; k++) acc += p[k] * w[j * 128 + k];
    out[j] = acc;
}

// ---------------- weight prep: fp32 -> {hi,lo} bf16, plain row-major ------------
__global__ void k_prep(const float* __restrict__ u_in_w, const float* __restrict__ i_in_w,
                       const float* __restrict__ u_out_w, const float* __restrict__ i_out_w) {
    int m = blockIdx.x;
    const float* src;
    switch (m) {
        case 0: src = u_in_w; break;
        case 1: src = u_in_w + 16384; break;
        case 2: src = u_in_w + 32768; break;
        case 3: src = i_in_w; break;
        case 4: src = i_in_w + 16384; break;
        case 5: src = i_in_w + 32768; break;
        case 6: src = u_out_w; break;
        default: src = i_out_w; break;
    }
    for (int idx = threadIdx.x; idx < 16384; idx += 256) {
        float x = src[idx];
        __nv_bfloat16 h = __float2bfloat16(x);
        __nv_bfloat16 l = __float2bfloat16(x - __bfloat162float(h));
        g_Bh[m * 16384 + idx] = h;
        g_Bl[m * 16384 + idx] = l;
    }
}

// ---------------- fused in-projection: one A tile x 6 weights (mma.sync bf16) ---
// smem: Ah[128][136] + Al[128][136] + Bs[128][136] bf16 = 104448 B
__global__ void __launch_bounds__(256) k_mma_in(const float* __restrict__ u_in_b,
                                                const float* __restrict__ i_in_b) {
    extern __shared__ __align__(16) __nv_bfloat16 smp[];
    __nv_bfloat16* AhS = smp;
    __nv_bfloat16* AlS = smp + 128 * ASTRIDE;
    __nv_bfloat16* BsS = smp + 2 * 128 * ASTRIDE;
    const uint32_t ahA = smem_to_u32(AhS), alA = smem_to_u32(AlS), bA = smem_to_u32(BsS);
    const int t = threadIdx.x, lane = t & 31, wid = t >> 5;
    const int warp_m = wid >> 2, warp_n = wid & 3;
    const int row0 = blockIdx.x * 128;

    stage_A(AhS, AlS, g_tmp, row0, Nn, t);

    for (int j = 0; j < 6; j++) {
        float acc[16][4];
        #pragma unroll
        for (int i = 0; i < 16; i++) { acc[i][0] = 0.f; acc[i][1] = 0.f; acc[i][2] = 0.f; acc[i][3] = 0.f; }

        __syncthreads();                       // Bs free (prev readers done); A staged
        stage_B(BsS, &g_Bh[j * 16384], t);
        __syncthreads();
        mma_phase(ahA, alA, bA, warp_m, warp_n, lane, acc);   // AhBh + AlBh
        __syncthreads();
        stage_B(BsS, &g_Bl[j * 16384], t);
        __syncthreads();
        mma_phase(ahA, 0, bA, warp_m, warp_n, lane, acc);     // AhBl

        float* outp;
        const float* bias;
        switch (j) {
            case 0: outp = g_QT;            bias = u_in_b;        break;
            case 1: outp = g_KT;            bias = u_in_b + 128;  break;
            case 2: outp = g_VT;            bias = u_in_b + 256;  break;
            case 3: outp = g_QT + Nn * Dd;  bias = i_in_b;        break;
            case 4: outp = g_KT + Nn * Dd;  bias = i_in_b + 128;  break;
            default: outp = g_VT + Nn * Dd; bias = i_in_b + 256;  break;
        }
        const int g = lane >> 2, q = lane & 3;
        #pragma unroll
        for (int tm = 0; tm < 4; tm++) {
            int r_ = row0 + warp_m * 64 + tm * 16 + g;
            #pragma unroll
            for (int tn = 0; tn < 4; tn++) {
                int c_ = warp_n * 32 + tn * 8 + 2 * q;
                float2 bv = *(const float2*)&bias[c_];
                float* a4 = acc[tm * 4 + tn];
                *(float2*)&outp[(size_t)r_ * 128 + c_]       = make_float2(a4[0] + bv.x, a4[1] + bv.y);
                *(float2*)&outp[(size_t)(r_ + 8) * 128 + c_] = make_float2(a4[2] + bv.x, a4[3] + bv.y);
            }
        }
    }
}

// ---------------- out-projection + residual + total (mma.sync bf16) -------------
__global__ void __launch_bounds__(256) k_mma_out(const float* __restrict__ u_out_b,
                                                 const float* __restrict__ i_out_b) {
    extern __shared__ __align__(16) __nv_bfloat16 smp[];
    __nv_bfloat16* AhS = smp;
    __nv_bfloat16* AlS = smp + 128 * ASTRIDE;
    __nv_bfloat16* BsS = smp + 2 * 128 * ASTRIDE;
    const uint32_t ahA = smem_to_u32(AhS), alA = smem_to_u32(AlS), bA = smem_to_u32(BsS);
    const int t = threadIdx.x, lane = t & 31, wid = t >> 5;
    const int warp_m = wid >> 2, warp_n = wid & 3;

    const int set = (blockIdx.x >= 313) ? 1 : 0;
    const int bb = set ? (blockIdx.x - 313) : blockIdx.x;
    const int row0 = set * Uu + bb * 128;
    const int limit = set ? Nn : Uu;
    const int m = 6 + set;
    const float* bias = set ? i_out_b : u_out_b;

    stage_A(AhS, AlS, g_O, row0, limit, t);

    float acc[16][4];
    #pragma unroll
    for (int i = 0; i < 16; i++) { acc[i][0] = 0.f; acc[i][1] = 0.f; acc[i][2] = 0.f; acc[i][3] = 0.f; }

    stage_B(BsS, &g_Bh[m * 16384], t);
    __syncthreads();
    mma_phase(ahA, alA, bA, warp_m, warp_n, lane, acc);
    __syncthreads();
    stage_B(BsS, &g_Bl[m * 16384], t);
    __syncthreads();
    mma_phase(ahA, 0, bA, warp_m, warp_n, lane, acc);

    const int g = lane >> 2, q = lane & 3;
    #pragma unroll
    for (int tm = 0; tm < 4; tm++) {
        #pragma unroll
        for (int tn = 0; tn < 4; tn++) {
            int c_ = warp_n * 32 + tn * 8 + 2 * q;
            float2 bv = *(const float2*)&bias[c_];
            float* a4 = acc[tm * 4 + tn];
            #pragma unroll
            for (int hrow = 0; hrow < 2; hrow++) {
                int r_ = row0 + warp_m * 64 + tm * 16 + g + hrow * 8;
                if (r_ >= limit) continue;
                size_t ofs = (size_t)r_ * 128 + c_;
                float2 rs = *(const float2*)&g_tmp[ofs];
                float ox = a4[hrow * 2 + 0] + bv.x + rs.x;
                float oy = a4[hrow * 2 + 1] + bv.y + rs.y;
                *(float2*)&g_e[ofs] = make_float2(ox, oy);
                float2 tv = *(const float2*)&g_total[ofs];
                *(float2*)&g_total[ofs] = make_float2(tv.x + ox, tv.y + oy);
            }
        }
    }
}

// ---------------- attention: one warp per node ----------------
__global__ void __launch_bounds__(256) k_attn(const int* __restrict__ samples) {
    int w = (blockIdx.x * 256 + threadIdx.x) >> 5;
    if (w >= Nn) return;
    int lane = threadIdx.x & 31;
    int set = (w < Uu) ? 0 : 1;
    const float* Qt = &g_QT[set * (Nn * Dd)];
    const float* Kt = &g_KT[set * (Nn * Dd)];
    const float* Vt = &g_VT[set * (Nn * Dd)];
    const float* pk = &g_posK[set * Lh * Dd];
    const float* pv = &g_posV[set * Lh * Dd];
    const float* pq = &g_posQ0[set * Dd];
    int c4 = lane * 4;

    float4 qv = *(const float4*)&Qt[w * Dd + c4];
    float4 pqv = *(const float4*)&pq[c4];
    float qx = qv.x + pqv.x, qy = qv.y + pqv.y, qz = qv.z + pqv.z, qw = qv.w + pqv.w;

    int sidx[Lh];
    sidx[0] = w;
    #pragma unroll
    for (int l = 1; l < Lh; l++) sidx[l] = samples[w * 16 + (l - 1)];

    const float scale = 0.17677669529663687f;
    float sc[Lh];
    #pragma unroll
    for (int l = 0; l < Lh; l++) {
        float4 kv = *(const float4*)&Kt[sidx[l] * Dd + c4];
        float4 pkv = *(const float4*)&pk[l * Dd + c4];
        float d = qx * (kv.x + pkv.x) + qy * (kv.y + pkv.y) + qz * (kv.z + pkv.z) + qw * (kv.w + pkv.w);
        d += __shfl_xor_sync(0xffffffffu, d, 1);
        d += __shfl_xor_sync(0xffffffffu, d, 2);
        d += __shfl_xor_sync(0xffffffffu, d, 4);
        sc[l] = d * scale;
    }
    float m = sc[0];
    #pragma unroll
    for (int l = 1; l < Lh; l++) m = fmaxf(m, sc[l]);
    float s = 0.f;
    #pragma unroll
    for (int l = 0; l < Lh; l++) { sc[l] = __expf(sc[l] - m); s += sc[l]; }
    float inv = 1.f / s;

    float ox = 0.f, oy = 0.f, oz = 0.f, ow = 0.f;
    #pragma unroll
    for (int l = 0; l < Lh; l++) {
        float wgt = sc[l] * inv;
        float4 vv = *(const float4*)&Vt[sidx[l] * Dd + c4];
        float4 pvv = *(const float4*)&pv[l * Dd + c4];
        ox += wgt * (vv.x + pvv.x); oy += wgt * (vv.y + pvv.y);
        oz += wgt * (vv.z + pvv.z); ow += wgt * (vv.w + pvv.w);
    }
    *(float4*)&g_O[w * Dd + c4] = make_float4(ox, oy, oz, ow);
}

// ---------------- output ----------------
__global__ void k_out(float* __restrict__ out) {
    int i = blockIdx.x * blockDim.x + threadIdx.x;
    if (i >= Nn * Dd) return;
    float v = g_total[i];
    out[i] = v;
    out[Nn * Dd + i] = v;
}

extern "C" void kernel_launch(void* const* d_in, const int* in_sizes, int n_in,
                              void* d_out, int out_size) {
    (void)in_sizes; (void)n_in; (void)out_size;
    const int*   adj_rows = (const int*)d_in[0];
    const int*   adj_cols = (const int*)d_in[1];
    const float* adj_vals = (const float*)d_in[2];
    const int*   samples  = (const int*)d_in[3];
    const float* user_emb = (const float*)d_in[4];
    const float* item_emb = (const float*)d_in[5];
    const float* pos_emb  = (const float*)d_in[6];
    const float* u_in_w   = (const float*)d_in[7];
    const float* u_in_b   = (const float*)d_in[8];
    const float* u_out_w  = (const float*)d_in[9];
    const float* u_out_b  = (const float*)d_in[10];
    const float* i_in_w   = (const float*)d_in[11];
    const float* i_in_b   = (const float*)d_in[12];
    const float* i_out_w  = (const float*)d_in[13];
    const float* i_out_b  = (const float*)d_in[14];
    float* out = (float*)d_out;

    const int SMB = 3 * 128 * ASTRIDE * (int)sizeof(__nv_bfloat16);  // 104448
    cudaFuncSetAttribute(k_mma_in,  cudaFuncAttributeMaxDynamicSharedMemorySize, SMB);
    cudaFuncSetAttribute(k_mma_out, cudaFuncAttributeMaxDynamicSharedMemorySize, SMB);

    void* cntP;
    cudaGetSymbolAddress(&cntP, g_cnt);

    // CSR build (constant per call; rebuilt for determinism)
    cudaMemsetAsync(cntP, 0, Nn * sizeof(int));
    k_hist<<<(Ee + 255) / 256, 256>>>(adj_rows);
    k_scan<<<1, 1024>>>();
    cudaMemsetAsync(cntP, 0, Nn * sizeof(int));
    k_scatter<<<(Ee + 255) / 256, 256>>>(adj_rows, adj_cols, adj_vals);

    k_init<<<(Nn * Dd) / 256, 256>>>(user_emb, item_emb);
    k_pos<<<70, 128>>>(pos_emb, u_in_w, i_in_w);
    k_prep<<<8, 256>>>(u_in_w, i_in_w, u_out_w, i_out_w);

    for (int blk = 0; blk < 2; blk++) {
        k_spmm<<<(Nn * 32) / 256, 256>>>();
        k_mma_in<<<Nn / 128, 256, SMB>>>(u_in_b, i_in_b);
        k_attn<<<(Nn * 32) / 256, 256>>>(samples);
        k_mma_out<<<626, 256, SMB>>>(u_out_b, i_out_b);
    }
    k_out<<<(Nn * Dd) / 256, 256>>>(out);
}